// round 1
// baseline (speedup 1.0000x reference)
#include <cuda_runtime.h>
#include <cstddef>

// Problem constants (fixed by the reference)
#define BB 64
#define TT 2048
#define DIN 128
#define HH 512
#define DOUT 128
#define MM (BB * TT)   // 131072

// Scratch: two [M, H] fp32 buffers (ping-pong). Static __device__ arrays are
// the allocation-guard-safe scratch mechanism.
__device__ float g_buf0[(size_t)MM * HH];
__device__ float g_buf1[(size_t)MM * HH];

// ---------------------------------------------------------------------------
// GEMM (NT): C[M,N] = A[M,K] * B[N,K]^T + bias1[N] (+ bias2[N] if non-null)
// A row-major K-contiguous, B row-major K-contiguous.
// Block tile 128x128, K-step 16, 256 threads, 8x8 per-thread microtile.
// Requires M%128==0, N%128==0, K%16==0 (true for all three GEMMs here).
// ---------------------------------------------------------------------------
__global__ __launch_bounds__(256, 2)
void gemm_nt_bias(const float* __restrict__ A,
                  const float* __restrict__ Bw,
                  const float* __restrict__ bias1,
                  const float* __restrict__ bias2,
                  float* __restrict__ C,
                  int M, int N, int K)
{
    constexpr int BM = 128, BN = 128, BK = 16;
    __shared__ float As[BK][BM + 2];
    __shared__ float Bs[BK][BN + 2];

    const int tid = threadIdx.x;
    const int bm = blockIdx.y * BM;
    const int bn = blockIdx.x * BN;
    const int tx = tid & 15;        // 0..15 -> N direction
    const int ty = tid >> 4;        // 0..15 -> M direction

    // Global->smem load mapping: each thread loads 2 float4 from A and 2 from B.
    const int lrow  = tid >> 2;         // 0..63
    const int lquad = (tid & 3) * 4;    // 0,4,8,12 (k offset within tile)

    const float* Ap0 = A  + (size_t)(bm + lrow)      * K + lquad;
    const float* Ap1 = A  + (size_t)(bm + lrow + 64) * K + lquad;
    const float* Bp0 = Bw + (size_t)(bn + lrow)      * K + lquad;
    const float* Bp1 = Bw + (size_t)(bn + lrow + 64) * K + lquad;

    float acc[8][8];
    #pragma unroll
    for (int i = 0; i < 8; i++)
        #pragma unroll
        for (int j = 0; j < 8; j++)
            acc[i][j] = 0.0f;

    for (int k0 = 0; k0 < K; k0 += BK) {
        float4 a0 = *(const float4*)(Ap0 + k0);
        float4 a1 = *(const float4*)(Ap1 + k0);
        float4 b0 = *(const float4*)(Bp0 + k0);
        float4 b1 = *(const float4*)(Bp1 + k0);

        __syncthreads();  // previous tile's compute must be done before overwrite

        As[lquad + 0][lrow]      = a0.x;
        As[lquad + 1][lrow]      = a0.y;
        As[lquad + 2][lrow]      = a0.z;
        As[lquad + 3][lrow]      = a0.w;
        As[lquad + 0][lrow + 64] = a1.x;
        As[lquad + 1][lrow + 64] = a1.y;
        As[lquad + 2][lrow + 64] = a1.z;
        As[lquad + 3][lrow + 64] = a1.w;

        Bs[lquad + 0][lrow]      = b0.x;
        Bs[lquad + 1][lrow]      = b0.y;
        Bs[lquad + 2][lrow]      = b0.z;
        Bs[lquad + 3][lrow]      = b0.w;
        Bs[lquad + 0][lrow + 64] = b1.x;
        Bs[lquad + 1][lrow + 64] = b1.y;
        Bs[lquad + 2][lrow + 64] = b1.z;
        Bs[lquad + 3][lrow + 64] = b1.w;

        __syncthreads();

        #pragma unroll
        for (int k = 0; k < BK; k++) {
            float ar[8], br[8];
            #pragma unroll
            for (int i = 0; i < 8; i++) ar[i] = As[k][ty * 8 + i];
            #pragma unroll
            for (int j = 0; j < 8; j++) br[j] = Bs[k][tx * 8 + j];
            #pragma unroll
            for (int i = 0; i < 8; i++)
                #pragma unroll
                for (int j = 0; j < 8; j++)
                    acc[i][j] = fmaf(ar[i], br[j], acc[i][j]);
        }
    }

    // Epilogue: add bias, vectorized stores
    float bsum[8];
    #pragma unroll
    for (int j = 0; j < 8; j++) {
        int n = bn + tx * 8 + j;
        float bv = bias1 ? bias1[n] : 0.0f;
        if (bias2) bv += bias2[n];
        bsum[j] = bv;
    }

    #pragma unroll
    for (int i = 0; i < 8; i++) {
        int m = bm + ty * 8 + i;
        float* crow = C + (size_t)m * N + bn + tx * 8;
        float4 v0, v1;
        v0.x = acc[i][0] + bsum[0];
        v0.y = acc[i][1] + bsum[1];
        v0.z = acc[i][2] + bsum[2];
        v0.w = acc[i][3] + bsum[3];
        v1.x = acc[i][4] + bsum[4];
        v1.y = acc[i][5] + bsum[5];
        v1.z = acc[i][6] + bsum[6];
        v1.w = acc[i][7] + bsum[7];
        *(float4*)(crow)     = v0;
        *(float4*)(crow + 4) = v1;
    }
}

// ---------------------------------------------------------------------------
// In-place IndRNN scan: P[b,t,h] <- h_t = relu(P[b,t,h] + u[h] * h_{t-1}), h_{-1}=0
// One thread per (b,h) channel; consecutive threads -> consecutive h (coalesced).
// Unroll-8 so loads issue ahead of the dependent fma/max chain.
// ---------------------------------------------------------------------------
__global__ void scan_relu(float* __restrict__ P, const float* __restrict__ u)
{
    int idx = blockIdx.x * blockDim.x + threadIdx.x;
    if (idx >= BB * HH) return;
    int b = idx / HH;
    int h = idx - b * HH;
    float uu = u[h];
    float hv = 0.0f;
    float* p = P + (size_t)b * TT * HH + h;

    constexpr int U = 8;
    #pragma unroll 1
    for (int t = 0; t < TT; t += U) {
        float x[U];
        #pragma unroll
        for (int i = 0; i < U; i++) x[i] = p[(size_t)i * HH];
        #pragma unroll
        for (int i = 0; i < U; i++) {
            hv = fmaxf(fmaf(uu, hv, x[i]), 0.0f);
            p[(size_t)i * HH] = hv;
        }
        p += (size_t)U * HH;
    }
}

extern "C" void kernel_launch(void* const* d_in, const int* in_sizes, int n_in,
                              void* d_out, int out_size)
{
    const float* x    = (const float*)d_in[0];
    const float* W0   = (const float*)d_in[1];
    const float* bl0  = (const float*)d_in[2];
    const float* u0   = (const float*)d_in[3];
    const float* bb0  = (const float*)d_in[4];
    const float* W1   = (const float*)d_in[5];
    const float* bl1  = (const float*)d_in[6];
    const float* u1   = (const float*)d_in[7];
    const float* bb1  = (const float*)d_in[8];
    const float* fcW  = (const float*)d_in[9];
    const float* fcb  = (const float*)d_in[10];
    float* out = (float*)d_out;

    float *buf0, *buf1;
    cudaGetSymbolAddress((void**)&buf0, g_buf0);
    cudaGetSymbolAddress((void**)&buf1, g_buf1);

    // GEMM0: proj0 = x @ W0^T + bl0 + bb0   [M, H]
    {
        dim3 grid(HH / 128, MM / 128);
        gemm_nt_bias<<<grid, 256>>>(x, W0, bl0, bb0, buf0, MM, HH, DIN);
    }
    // Scan0 (in-place on buf0) -> h1
    scan_relu<<<(BB * HH) / 256, 256>>>(buf0, u0);

    // GEMM1: proj1 = h1 @ W1^T + bl1 + bb1
    {
        dim3 grid(HH / 128, MM / 128);
        gemm_nt_bias<<<grid, 256>>>(buf0, W1, bl1, bb1, buf1, MM, HH, HH);
    }
    // Scan1 (in-place on buf1) -> h2
    scan_relu<<<(BB * HH) / 256, 256>>>(buf1, u1);

    // GEMM2: out = h2 @ fcW^T + fcb   [M, Dout]
    {
        dim3 grid(DOUT / 128, MM / 128);
        gemm_nt_bias<<<grid, 256>>>(buf1, fcW, fcb, nullptr, out, MM, DOUT, HH);
    }
}

// round 3
// speedup vs baseline: 1.7384x; 1.7384x over previous
#include <cuda_runtime.h>
#include <cuda_bf16.h>
#include <cstdint>
#include <cstddef>

// Problem constants (fixed by the reference)
#define BB 64
#define TT 2048
#define DIN 128
#define HH 512
#define DOUT 128
#define MM (BB * TT)   // 131072

// Scratch: two [M, H] fp32 buffers (ping-pong).
__device__ float g_buf0[(size_t)MM * HH];
__device__ float g_buf1[(size_t)MM * HH];

// ---------------------------------------------------------------------------
// bf16 split helpers: x ~= hi + lo, each bf16. Error ~2^-18 * |x|.
// ---------------------------------------------------------------------------
__device__ __forceinline__ void split_pack(float x, float y,
                                           uint32_t& hi, uint32_t& lo) {
    __nv_bfloat16 hx = __float2bfloat16(x);
    __nv_bfloat16 hy = __float2bfloat16(y);
    __nv_bfloat16 lx = __float2bfloat16(x - __bfloat162float(hx));
    __nv_bfloat16 ly = __float2bfloat16(y - __bfloat162float(hy));
    __nv_bfloat162 h2; h2.x = hx; h2.y = hy;
    __nv_bfloat162 l2; l2.x = lx; l2.y = ly;
    hi = *reinterpret_cast<uint32_t*>(&h2);
    lo = *reinterpret_cast<uint32_t*>(&l2);
}

// mma.sync m16n8k16 row.col f32.bf16.bf16.f32, accumulate in place
__device__ __forceinline__ void mma_bf16(float* c,
                                         uint32_t a0, uint32_t a1,
                                         uint32_t a2, uint32_t a3,
                                         uint32_t b0, uint32_t b1) {
    asm volatile(
        "mma.sync.aligned.m16n8k16.row.col.f32.bf16.bf16.f32 "
        "{%0,%1,%2,%3}, {%4,%5,%6,%7}, {%8,%9}, {%0,%1,%2,%3};"
        : "+f"(c[0]), "+f"(c[1]), "+f"(c[2]), "+f"(c[3])
        : "r"(a0), "r"(a1), "r"(a2), "r"(a3), "r"(b0), "r"(b1));
}

// ---------------------------------------------------------------------------
// Tensor-core 3-term bf16-split GEMM (NT):
//   C[M,N] = A[M,K] * B[N,K]^T + bias1[N] (+ bias2[N] if non-null)
// Block tile 128x128, BK=32, 8 warps (2x4), warp tile 64x32 (4x4 mma tiles).
// Double-buffered smem; fp32->bf16hi/lo split done in the load stage.
// Requires M%128==0, N%128==0, K%32==0.
// ---------------------------------------------------------------------------
// smem: bias 512B @0; tiles @1024. Per stage: Ahi,Alo,Bhi,Blo each 128 rows
// x 80B (32 bf16 = 64B data + 16B pad; pad makes fragment LDS conflict-free).
#define TILE_B   (128 * 80)                 // 10240
#define STAGE_B  (4 * TILE_B)               // 40960
#define SMEM_GEMM (1024 + 2 * STAGE_B)      // 82944

__global__ __launch_bounds__(256)
void gemm_bf16x3(const float* __restrict__ A,
                 const float* __restrict__ Bw,
                 const float* __restrict__ bias1,
                 const float* __restrict__ bias2,
                 float* __restrict__ C,
                 int M, int N, int K)
{
    extern __shared__ char smem[];
    float* biasS = (float*)smem;
    char* tiles = smem + 1024;

    const int tid  = threadIdx.x;
    const int wid  = tid >> 5;
    const int lane = tid & 31;
    const int bm = blockIdx.y * 128;
    const int bn = blockIdx.x * 128;

    // warp layout: 2 (M) x 4 (N); warp tile 64x32
    const int wm = (wid >> 2) * 64;
    const int wn = (wid & 3) * 32;
    const int g0 = lane >> 2;          // fragment row within 16
    const int qk = (lane & 3);         // fragment k-quad

    // gmem load mapping: thread -> (row = tid>>1, half = tid&1), 4 float4 each
    const int lrow  = tid >> 1;        // 0..127
    const int lhalf = tid & 1;         // k offset 0 or 16

    if (tid < 128) {
        float bv = bias1 ? bias1[bn + tid] : 0.0f;
        if (bias2) bv += bias2[bn + tid];
        biasS[tid] = bv;
    }

    const float* Ag = A  + (size_t)(bm + lrow) * K + lhalf * 16;
    const float* Bg = Bw + (size_t)(bn + lrow) * K + lhalf * 16;

    float acc[4][4][4];
    #pragma unroll
    for (int mt = 0; mt < 4; mt++)
        #pragma unroll
        for (int nt = 0; nt < 4; nt++)
            #pragma unroll
            for (int j = 0; j < 4; j++)
                acc[mt][nt][j] = 0.0f;

    const int NK = K >> 5;

    float4 ar[4], br[4];
    // prefetch stage 0
    #pragma unroll
    for (int q = 0; q < 4; q++) {
        ar[q] = *(const float4*)(Ag + q * 4);
        br[q] = *(const float4*)(Bg + q * 4);
    }

    for (int kt = 0; kt < NK; kt++) {
        const int p = kt & 1;
        char* st = tiles + p * STAGE_B;
        char* sAhi = st;
        char* sAlo = st + TILE_B;
        char* sBhi = st + 2 * TILE_B;
        char* sBlo = st + 3 * TILE_B;

        __syncthreads();   // consumers of this buffer (kt-2) are done

        // convert + store (8B chunks, 16B-aligned rows)
        {
            const int off = lrow * 80 + lhalf * 32;
            #pragma unroll
            for (int q = 0; q < 4; q++) {
                uint32_t h0, l0, h1, l1;
                split_pack(ar[q].x, ar[q].y, h0, l0);
                split_pack(ar[q].z, ar[q].w, h1, l1);
                *(uint2*)(sAhi + off + q * 8) = make_uint2(h0, h1);
                *(uint2*)(sAlo + off + q * 8) = make_uint2(l0, l1);
                split_pack(br[q].x, br[q].y, h0, l0);
                split_pack(br[q].z, br[q].w, h1, l1);
                *(uint2*)(sBhi + off + q * 8) = make_uint2(h0, h1);
                *(uint2*)(sBlo + off + q * 8) = make_uint2(l0, l1);
            }
        }

        __syncthreads();

        // prefetch next stage (gmem latency overlaps the mma below)
        if (kt + 1 < NK) {
            const float* Agn = Ag + (kt + 1) * 32;
            const float* Bgn = Bg + (kt + 1) * 32;
            #pragma unroll
            for (int q = 0; q < 4; q++) {
                ar[q] = *(const float4*)(Agn + q * 4);
                br[q] = *(const float4*)(Bgn + q * 4);
            }
        }

        // MMA over this stage: 2 k16-steps
        #pragma unroll
        for (int ko = 0; ko < 2; ko++) {
            const int kb = ko * 32 + qk * 4;   // byte offset of k-pair

            uint32_t Ahi[4][4], Alo[4][4];
            #pragma unroll
            for (int mt = 0; mt < 4; mt++) {
                int r0 = (wm + mt * 16 + g0) * 80 + kb;
                Ahi[mt][0] = *(const uint32_t*)(sAhi + r0);
                Ahi[mt][1] = *(const uint32_t*)(sAhi + r0 + 8 * 80);
                Ahi[mt][2] = *(const uint32_t*)(sAhi + r0 + 16);
                Ahi[mt][3] = *(const uint32_t*)(sAhi + r0 + 8 * 80 + 16);
                Alo[mt][0] = *(const uint32_t*)(sAlo + r0);
                Alo[mt][1] = *(const uint32_t*)(sAlo + r0 + 8 * 80);
                Alo[mt][2] = *(const uint32_t*)(sAlo + r0 + 16);
                Alo[mt][3] = *(const uint32_t*)(sAlo + r0 + 8 * 80 + 16);
            }
            uint32_t Bhi[4][2], Blo[4][2];
            #pragma unroll
            for (int nt = 0; nt < 4; nt++) {
                int r0 = (wn + nt * 8 + g0) * 80 + kb;
                Bhi[nt][0] = *(const uint32_t*)(sBhi + r0);
                Bhi[nt][1] = *(const uint32_t*)(sBhi + r0 + 16);
                Blo[nt][0] = *(const uint32_t*)(sBlo + r0);
                Blo[nt][1] = *(const uint32_t*)(sBlo + r0 + 16);
            }
            #pragma unroll
            for (int mt = 0; mt < 4; mt++)
                #pragma unroll
                for (int nt = 0; nt < 4; nt++) {
                    float* c = acc[mt][nt];
                    mma_bf16(c, Ahi[mt][0], Ahi[mt][1], Ahi[mt][2], Ahi[mt][3],
                             Bhi[nt][0], Bhi[nt][1]);
                    mma_bf16(c, Ahi[mt][0], Ahi[mt][1], Ahi[mt][2], Ahi[mt][3],
                             Blo[nt][0], Blo[nt][1]);
                    mma_bf16(c, Alo[mt][0], Alo[mt][1], Alo[mt][2], Alo[mt][3],
                             Bhi[nt][0], Bhi[nt][1]);
                }
        }
    }

    // Epilogue: bias + store (float2 per fragment row-pair)
    const int c0 = (lane & 3) * 2;
    #pragma unroll
    for (int mt = 0; mt < 4; mt++) {
        #pragma unroll
        for (int nt = 0; nt < 4; nt++) {
            int colL = wn + nt * 8 + c0;
            int col  = bn + colL;
            float b0v = biasS[colL];
            float b1v = biasS[colL + 1];
            int row0 = bm + wm + mt * 16 + g0;
            float2 v0 = make_float2(acc[mt][nt][0] + b0v, acc[mt][nt][1] + b1v);
            float2 v1 = make_float2(acc[mt][nt][2] + b0v, acc[mt][nt][3] + b1v);
            *(float2*)(C + (size_t)row0 * N + col)       = v0;
            *(float2*)(C + (size_t)(row0 + 8) * N + col) = v1;
        }
    }
}

// ---------------------------------------------------------------------------
// In-place IndRNN scan: P[b,t,h] <- relu(P[b,t,h] + u[h]*h_prev), h_{-1}=0.
// U=16 with next-block prefetch to double MLP (it was latency-bound).
// ---------------------------------------------------------------------------
__global__ void scan_relu(float* __restrict__ P, const float* __restrict__ u)
{
    int idx = blockIdx.x * blockDim.x + threadIdx.x;
    if (idx >= BB * HH) return;
    int b = idx / HH;
    int h = idx - b * HH;
    float uu = u[h];
    float hv = 0.0f;
    float* p = P + (size_t)b * TT * HH + h;

    constexpr int U = 16;
    float x[U];
    #pragma unroll
    for (int i = 0; i < U; i++) x[i] = p[(size_t)i * HH];

    #pragma unroll 1
    for (int t = 0; t < TT; t += U) {
        float y[U];
        bool more = (t + U) < TT;
        float* pn = p + (size_t)U * HH;
        if (more) {
            #pragma unroll
            for (int i = 0; i < U; i++) y[i] = pn[(size_t)i * HH];
        }
        #pragma unroll
        for (int i = 0; i < U; i++) {
            hv = fmaxf(fmaf(uu, hv, x[i]), 0.0f);
            p[(size_t)i * HH] = hv;
        }
        #pragma unroll
        for (int i = 0; i < U; i++) x[i] = y[i];
        p = pn;
    }
}

extern "C" void kernel_launch(void* const* d_in, const int* in_sizes, int n_in,
                              void* d_out, int out_size)
{
    const float* x    = (const float*)d_in[0];
    const float* W0   = (const float*)d_in[1];
    const float* bl0  = (const float*)d_in[2];
    const float* u0   = (const float*)d_in[3];
    const float* bb0  = (const float*)d_in[4];
    const float* W1   = (const float*)d_in[5];
    const float* bl1  = (const float*)d_in[6];
    const float* u1   = (const float*)d_in[7];
    const float* bb1  = (const float*)d_in[8];
    const float* fcW  = (const float*)d_in[9];
    const float* fcb  = (const float*)d_in[10];
    float* out = (float*)d_out;

    float *buf0, *buf1;
    cudaGetSymbolAddress((void**)&buf0, g_buf0);
    cudaGetSymbolAddress((void**)&buf1, g_buf1);

    cudaFuncSetAttribute(gemm_bf16x3,
                         cudaFuncAttributeMaxDynamicSharedMemorySize,
                         SMEM_GEMM);

    // GEMM0: proj0 = x @ W0^T + bl0 + bb0   [M, H], K=128
    {
        dim3 grid(HH / 128, MM / 128);
        gemm_bf16x3<<<grid, 256, SMEM_GEMM>>>(x, W0, bl0, bb0, buf0, MM, HH, DIN);
    }
    scan_relu<<<(BB * HH) / 128, 128>>>(buf0, u0);

    // GEMM1: proj1 = h1 @ W1^T + bl1 + bb1  [M, H], K=512
    {
        dim3 grid(HH / 128, MM / 128);
        gemm_bf16x3<<<grid, 256, SMEM_GEMM>>>(buf0, W1, bl1, bb1, buf1, MM, HH, HH);
    }
    scan_relu<<<(BB * HH) / 128, 128>>>(buf1, u1);

    // GEMM2: out = h2 @ fcW^T + fcb  [M, Dout], K=512
    {
        dim3 grid(DOUT / 128, MM / 128);
        gemm_bf16x3<<<grid, 256, SMEM_GEMM>>>(buf1, fcW, fcb, nullptr, out, MM, DOUT, HH);
    }
}

// round 5
// speedup vs baseline: 3.1051x; 1.7862x over previous
#include <cuda_runtime.h>
#include <cuda_fp16.h>
#include <cstdint>
#include <cstddef>

// Problem constants (fixed by the reference)
#define BB 64
#define TT 2048
#define DIN 128
#define HH 512
#define DOUT 128
#define MM (BB * TT)   // 131072

// Scratch buffers (allocation-guard-safe __device__ globals)
__device__ __align__(256) float  g_proj[(size_t)MM * HH];   // fp32 proj (both layers)
__device__ __align__(256) __half g_act[(size_t)MM * HH];    // fp16 activations (scaled)
__device__ __align__(256) __half g_x16[(size_t)MM * DIN];   // fp16 x
__device__ __align__(256) __half g_w0hi[HH * DIN], g_w0lo[HH * DIN];
__device__ __align__(256) __half g_w1hi[HH * HH],  g_w1lo[HH * HH];
__device__ __align__(256) __half g_fwhi[DOUT * HH], g_fwlo[DOUT * HH];

// ---------------------------------------------------------------------------
// PTX helpers
// ---------------------------------------------------------------------------
__device__ __forceinline__ uint32_t smem_u32(const void* p) {
    uint32_t a;
    asm("{ .reg .u64 t; cvta.to.shared.u64 t, %1; cvt.u32.u64 %0, t; }"
        : "=r"(a) : "l"(p));
    return a;
}

__device__ __forceinline__ void cp_async16(uint32_t dst, const void* src) {
    asm volatile("cp.async.cg.shared.global [%0], [%1], 16;"
                 :: "r"(dst), "l"(src));
}
#define CP_COMMIT() asm volatile("cp.async.commit_group;" ::: "memory")
#define CP_WAIT1()  asm volatile("cp.async.wait_group 1;" ::: "memory")

// mma m16n8k16 fp16 inputs, fp32 accumulate (in place)
__device__ __forceinline__ void mma_f16(float* c,
                                        uint32_t a0, uint32_t a1,
                                        uint32_t a2, uint32_t a3,
                                        uint32_t b0, uint32_t b1) {
    asm volatile(
        "mma.sync.aligned.m16n8k16.row.col.f32.f16.f16.f32 "
        "{%0,%1,%2,%3}, {%4,%5,%6,%7}, {%8,%9}, {%0,%1,%2,%3};"
        : "+f"(c[0]), "+f"(c[1]), "+f"(c[2]), "+f"(c[3])
        : "r"(a0), "r"(a1), "r"(a2), "r"(a3), "r"(b0), "r"(b1));
}

// ---------------------------------------------------------------------------
// fp16 2-term GEMM (NT): C[M,N] = out_scale * (A[M,K] * (Bhi+Blo)[N,K]^T)
//                                 + bias1[N] (+ bias2[N])
// A fp16 single; B pre-split fp16 hi/lo. Block 128x128, BK=32, 8 warps (2x4),
// warp tile 64x32. cp.async 3-stage pipeline. M%128==0, N%128==0, K%32==0,
// K/32 >= 2.
// smem rows: 32 fp16 = 64B data + 16B pad = 80B (conflict-free fragments).
// ---------------------------------------------------------------------------
#define ROWB   80
#define TILE_B (128 * ROWB)        // 10240
#define STAGE_B (3 * TILE_B)       // 30720 (A, Bhi, Blo)
#define NSTAGE 3
#define SMEM_GEMM (512 + NSTAGE * STAGE_B)   // 92672

__global__ __launch_bounds__(256, 2)
void gemm_f16_2t(const __half* __restrict__ A,
                 const __half* __restrict__ Bhi,
                 const __half* __restrict__ Blo,
                 const float* __restrict__ bias1,
                 const float* __restrict__ bias2,
                 float* __restrict__ C,
                 int M, int N, int K, float out_scale)
{
    extern __shared__ char smem[];
    float* biasS = (float*)smem;
    char* tiles = smem + 512;
    const uint32_t tilesU = smem_u32(tiles);

    const int tid  = threadIdx.x;
    const int wid  = tid >> 5;
    const int lane = tid & 31;
    const int bm = blockIdx.y * 128;
    const int bn = blockIdx.x * 128;

    const int wm = (wid >> 2) * 64;
    const int wn = (wid & 3) * 32;
    const int g0 = lane >> 2;
    const int qk = lane & 3;

    if (tid < 128) {
        float bv = bias1[bn + tid];
        if (bias2) bv += bias2[bn + tid];
        biasS[tid] = bv;
    }

    // cp.async mapping: thread -> rows (tid>>2) and (tid>>2)+64, col (tid&3)*16B
    const int crow = tid >> 2;
    const int ccol = (tid & 3) * 16;
    const size_t rstride = (size_t)K * 2;   // bytes per gmem row

    const char* Ag  = (const char*)A   + (size_t)(bm + crow) * rstride + ccol;
    const char* BHg = (const char*)Bhi + (size_t)(bn + crow) * rstride + ccol;
    const char* BLg = (const char*)Blo + (size_t)(bn + crow) * rstride + ccol;
    const size_t r64 = 64 * rstride;

    const uint32_t sbase = tilesU + crow * ROWB + (tid & 3) * 16;

    float acc[4][4][4];
    #pragma unroll
    for (int mt = 0; mt < 4; mt++)
        #pragma unroll
        for (int nt = 0; nt < 4; nt++)
            #pragma unroll
            for (int j = 0; j < 4; j++)
                acc[mt][nt][j] = 0.0f;

    const int NK = K >> 5;

    auto load_stage = [&](int s, int kt) {
        uint32_t d = sbase + s * STAGE_B;
        size_t go = (size_t)kt * 64;     // 32 fp16 = 64 bytes
        cp_async16(d,                 Ag  + go);
        cp_async16(d + 64 * ROWB,     Ag  + go + r64);
        cp_async16(d + TILE_B,            BHg + go);
        cp_async16(d + TILE_B + 64 * ROWB, BHg + go + r64);
        cp_async16(d + 2 * TILE_B,            BLg + go);
        cp_async16(d + 2 * TILE_B + 64 * ROWB, BLg + go + r64);
    };

    load_stage(0, 0); CP_COMMIT();
    load_stage(1, 1); CP_COMMIT();

    for (int kt = 0; kt < NK; kt++) {
        CP_WAIT1();          // stage kt landed
        __syncthreads();     // visible to all; prev iter's MMA done

        if (kt + 2 < NK) load_stage((kt + 2) % 3, kt + 2);
        CP_COMMIT();         // unconditional: keeps group counting aligned

        const char* st = tiles + (kt % 3) * STAGE_B;

        #pragma unroll
        for (int ko = 0; ko < 2; ko++) {
            const int kb = ko * 32 + qk * 4;

            uint32_t Af[4][4];
            #pragma unroll
            for (int mt = 0; mt < 4; mt++) {
                int r0 = (wm + mt * 16 + g0) * ROWB + kb;
                Af[mt][0] = *(const uint32_t*)(st + r0);
                Af[mt][1] = *(const uint32_t*)(st + r0 + 8 * ROWB);
                Af[mt][2] = *(const uint32_t*)(st + r0 + 16);
                Af[mt][3] = *(const uint32_t*)(st + r0 + 8 * ROWB + 16);
            }
            uint32_t Bh[4][2], Bl[4][2];
            #pragma unroll
            for (int nt = 0; nt < 4; nt++) {
                int r0 = TILE_B + (wn + nt * 8 + g0) * ROWB + kb;
                Bh[nt][0] = *(const uint32_t*)(st + r0);
                Bh[nt][1] = *(const uint32_t*)(st + r0 + 16);
                Bl[nt][0] = *(const uint32_t*)(st + r0 + TILE_B);
                Bl[nt][1] = *(const uint32_t*)(st + r0 + TILE_B + 16);
            }
            #pragma unroll
            for (int mt = 0; mt < 4; mt++)
                #pragma unroll
                for (int nt = 0; nt < 4; nt++) {
                    float* c = acc[mt][nt];
                    mma_f16(c, Af[mt][0], Af[mt][1], Af[mt][2], Af[mt][3],
                            Bh[nt][0], Bh[nt][1]);
                    mma_f16(c, Af[mt][0], Af[mt][1], Af[mt][2], Af[mt][3],
                            Bl[nt][0], Bl[nt][1]);
                }
        }
    }

    // Epilogue: scale + bias + float2 stores
    const int c0 = (lane & 3) * 2;
    #pragma unroll
    for (int mt = 0; mt < 4; mt++) {
        #pragma unroll
        for (int nt = 0; nt < 4; nt++) {
            int colL = wn + nt * 8 + c0;
            int col  = bn + colL;
            float b0v = biasS[colL];
            float b1v = biasS[colL + 1];
            int row0 = bm + wm + mt * 16 + g0;
            float2 v0 = make_float2(fmaf(acc[mt][nt][0], out_scale, b0v),
                                    fmaf(acc[mt][nt][1], out_scale, b1v));
            float2 v1 = make_float2(fmaf(acc[mt][nt][2], out_scale, b0v),
                                    fmaf(acc[mt][nt][3], out_scale, b1v));
            *(float2*)(C + (size_t)row0 * N + col)       = v0;
            *(float2*)(C + (size_t)(row0 + 8) * N + col) = v1;
        }
    }
}

// ---------------------------------------------------------------------------
// IndRNN scan, fp16 output with power-of-2 down-scaling (range protection):
//   O[b,t,h] = fp16( relu(P[b,t,h] + u[h]*h_prev) * store_scale )
// ---------------------------------------------------------------------------
__global__ void scan_relu_f16(const float* __restrict__ P,
                              const float* __restrict__ u,
                              __half* __restrict__ O,
                              float store_scale)
{
    int idx = blockIdx.x * blockDim.x + threadIdx.x;
    if (idx >= BB * HH) return;
    int b = idx / HH;
    int h = idx - b * HH;
    float uu = u[h];
    float hv = 0.0f;
    const float* p = P + (size_t)b * TT * HH + h;
    __half* o = O + (size_t)b * TT * HH + h;

    constexpr int U = 16;
    float x[U];
    #pragma unroll
    for (int i = 0; i < U; i++) x[i] = p[(size_t)i * HH];

    #pragma unroll 1
    for (int t = 0; t < TT; t += U) {
        float y[U];
        bool more = (t + U) < TT;
        const float* pn = p + (size_t)U * HH;
        if (more) {
            #pragma unroll
            for (int i = 0; i < U; i++) y[i] = pn[(size_t)i * HH];
        }
        #pragma unroll
        for (int i = 0; i < U; i++) {
            hv = fmaxf(fmaf(uu, hv, x[i]), 0.0f);
            o[(size_t)i * HH] = __float2half_rn(hv * store_scale);
        }
        #pragma unroll
        for (int i = 0; i < U; i++) x[i] = y[i];
        p = pn;
        o += (size_t)U * HH;
    }
}

// ---------------------------------------------------------------------------
// Converters
// ---------------------------------------------------------------------------
__global__ void f32_to_f16(const float* __restrict__ in,
                           __half* __restrict__ out, int n)
{
    int i = (blockIdx.x * blockDim.x + threadIdx.x) * 4;
    if (i < n) {
        float4 v = *(const float4*)(in + i);
        __half2 h0 = __floats2half2_rn(v.x, v.y);
        __half2 h1 = __floats2half2_rn(v.z, v.w);
        uint2 pk = make_uint2(*(uint32_t*)&h0, *(uint32_t*)&h1);
        *(uint2*)(out + i) = pk;
    }
}

__global__ void split_w_f16(const float* __restrict__ in,
                            __half* __restrict__ hi,
                            __half* __restrict__ lo, int n)
{
    int i = blockIdx.x * blockDim.x + threadIdx.x;
    if (i < n) {
        float w = in[i];
        __half h = __float2half_rn(w);
        hi[i] = h;
        lo[i] = __float2half_rn(w - __half2float(h));
    }
}

extern "C" void kernel_launch(void* const* d_in, const int* in_sizes, int n_in,
                              void* d_out, int out_size)
{
    const float* x    = (const float*)d_in[0];
    const float* W0   = (const float*)d_in[1];
    const float* bl0  = (const float*)d_in[2];
    const float* u0   = (const float*)d_in[3];
    const float* bb0  = (const float*)d_in[4];
    const float* W1   = (const float*)d_in[5];
    const float* bl1  = (const float*)d_in[6];
    const float* u1   = (const float*)d_in[7];
    const float* bb1  = (const float*)d_in[8];
    const float* fcW  = (const float*)d_in[9];
    const float* fcb  = (const float*)d_in[10];
    float* out = (float*)d_out;

    float  *proj;
    __half *act, *x16, *w0h, *w0l, *w1h, *w1l, *fwh, *fwl;
    cudaGetSymbolAddress((void**)&proj, g_proj);
    cudaGetSymbolAddress((void**)&act,  g_act);
    cudaGetSymbolAddress((void**)&x16,  g_x16);
    cudaGetSymbolAddress((void**)&w0h,  g_w0hi);
    cudaGetSymbolAddress((void**)&w0l,  g_w0lo);
    cudaGetSymbolAddress((void**)&w1h,  g_w1hi);
    cudaGetSymbolAddress((void**)&w1l,  g_w1lo);
    cudaGetSymbolAddress((void**)&fwh,  g_fwhi);
    cudaGetSymbolAddress((void**)&fwl,  g_fwlo);

    cudaFuncSetAttribute(gemm_f16_2t,
                         cudaFuncAttributeMaxDynamicSharedMemorySize,
                         SMEM_GEMM);

    // Pre-split weights (tiny)
    split_w_f16<<<(HH * DIN + 255) / 256, 256>>>(W0, w0h, w0l, HH * DIN);
    split_w_f16<<<(HH * HH + 255) / 256, 256>>>(W1, w1h, w1l, HH * HH);
    split_w_f16<<<(DOUT * HH + 255) / 256, 256>>>(fcW, fwh, fwl, DOUT * HH);

    // x -> fp16 (x ~ N(0,1): no range issue)
    {
        int n = MM * DIN;
        f32_to_f16<<<(n / 4 + 255) / 256, 256>>>(x, x16, n);
    }

    // GEMM0: proj = x16 @ W0^T + bl0 + bb0   [M, H], K=128
    {
        dim3 grid(HH / 128, MM / 128);
        gemm_f16_2t<<<grid, 256, SMEM_GEMM>>>(x16, w0h, w0l, bl0, bb0, proj,
                                              MM, HH, DIN, 1.0f);
    }
    // scan0 -> act = h1 * 2^-4  (h1 max ~few hundred; scaled well within fp16)
    scan_relu_f16<<<(BB * HH) / 128, 128>>>(proj, u0, act, 0.0625f);

    // GEMM1: proj = (h1*2^-4) @ W1^T * 16 + bl1 + bb1  [M, H], K=512
    {
        dim3 grid(HH / 128, MM / 128);
        gemm_f16_2t<<<grid, 256, SMEM_GEMM>>>(act, w1h, w1l, bl1, bb1, proj,
                                              MM, HH, HH, 16.0f);
    }
    // scan1 -> act = h2 * 2^-8  (h2 can reach ~1e5 unscaled -> fp16-safe scaled)
    scan_relu_f16<<<(BB * HH) / 128, 128>>>(proj, u1, act, 0.00390625f);

    // GEMM2: out = (h2*2^-8) @ fcW^T * 256 + fcb  [M, Dout], K=512
    {
        dim3 grid(DOUT / 128, MM / 128);
        gemm_f16_2t<<<grid, 256, SMEM_GEMM>>>(act, fwh, fwl, fcb, nullptr, out,
                                              MM, DOUT, HH, 256.0f);
    }
}

// round 6
// speedup vs baseline: 3.3321x; 1.0731x over previous
#include <cuda_runtime.h>
#include <cuda_fp16.h>
#include <cstdint>
#include <cstddef>

// Problem constants (fixed by the reference)
#define BB 64
#define TT 2048
#define DIN 128
#define HH 512
#define DOUT 128
#define MM (BB * TT)   // 131072

// Scratch buffers (allocation-guard-safe __device__ globals)
__device__ __align__(256) float  g_proj[(size_t)MM * HH];   // fp32 proj (both layers)
__device__ __align__(256) __half g_act[(size_t)MM * HH];    // fp16 activations (scaled)
__device__ __align__(256) __half g_x16[(size_t)MM * DIN];   // fp16 x
__device__ __align__(256) __half g_w0hi[HH * DIN], g_w0lo[HH * DIN];
__device__ __align__(256) __half g_w1hi[HH * HH],  g_w1lo[HH * HH];
__device__ __align__(256) __half g_fwhi[DOUT * HH], g_fwlo[DOUT * HH];

// ---------------------------------------------------------------------------
// PTX helpers
// ---------------------------------------------------------------------------
__device__ __forceinline__ uint32_t smem_u32(const void* p) {
    uint32_t a;
    asm("{ .reg .u64 t; cvta.to.shared.u64 t, %1; cvt.u32.u64 %0, t; }"
        : "=r"(a) : "l"(p));
    return a;
}

__device__ __forceinline__ void cp_async16(uint32_t dst, const void* src) {
    asm volatile("cp.async.cg.shared.global [%0], [%1], 16;"
                 :: "r"(dst), "l"(src));
}
#define CP_COMMIT() asm volatile("cp.async.commit_group;" ::: "memory")
#define CP_WAIT1()  asm volatile("cp.async.wait_group 1;" ::: "memory")

// mma m16n8k16 fp16 inputs, fp32 accumulate (in place)
__device__ __forceinline__ void mma_f16(float* c,
                                        uint32_t a0, uint32_t a1,
                                        uint32_t a2, uint32_t a3,
                                        uint32_t b0, uint32_t b1) {
    asm volatile(
        "mma.sync.aligned.m16n8k16.row.col.f32.f16.f16.f32 "
        "{%0,%1,%2,%3}, {%4,%5,%6,%7}, {%8,%9}, {%0,%1,%2,%3};"
        : "+f"(c[0]), "+f"(c[1]), "+f"(c[2]), "+f"(c[3])
        : "r"(a0), "r"(a1), "r"(a2), "r"(a3), "r"(b0), "r"(b1));
}

// ldmatrix x4 (b16): four 8x8 tiles, one per 8-lane group
__device__ __forceinline__ void ldsm_x4(uint32_t& r0, uint32_t& r1,
                                        uint32_t& r2, uint32_t& r3,
                                        uint32_t addr) {
    asm volatile("ldmatrix.sync.aligned.m8n8.x4.shared.b16 {%0,%1,%2,%3}, [%4];"
                 : "=r"(r0), "=r"(r1), "=r"(r2), "=r"(r3) : "r"(addr));
}

// ---------------------------------------------------------------------------
// fp16 2-term GEMM (NT): C[M,N] = out_scale * (A[M,K] * (Bhi+Blo)[N,K]^T)
//                                 + bias1[N] (+ bias2[N])
// Block 128x128, BK=32, 8 warps (2x4), warp tile 64x32.
// cp.async 3-stage pipeline; ldmatrix fragment loads.
// smem rows: 32 fp16 = 64B data + 16B pad = 80B (conflict-free LDSM phases).
// ---------------------------------------------------------------------------
#define ROWB   80
#define TILE_B (128 * ROWB)        // 10240
#define STAGE_B (3 * TILE_B)       // 30720 (A, Bhi, Blo)
#define NSTAGE 3
#define SMEM_GEMM (512 + NSTAGE * STAGE_B)   // 92672

__global__ __launch_bounds__(256, 2)
void gemm_f16_2t(const __half* __restrict__ A,
                 const __half* __restrict__ Bhi,
                 const __half* __restrict__ Blo,
                 const float* __restrict__ bias1,
                 const float* __restrict__ bias2,
                 float* __restrict__ C,
                 int M, int N, int K, float out_scale)
{
    extern __shared__ char smem[];
    float* biasS = (float*)smem;
    char* tiles = smem + 512;
    const uint32_t tilesU = smem_u32(tiles);

    const int tid  = threadIdx.x;
    const int wid  = tid >> 5;
    const int lane = tid & 31;
    const int bm = blockIdx.y * 128;
    const int bn = blockIdx.x * 128;

    const int wm = (wid >> 2) * 64;
    const int wn = (wid & 3) * 32;
    const int g0 = lane >> 2;

    if (tid < 128) {
        float bv = bias1[bn + tid];
        if (bias2) bv += bias2[bn + tid];
        biasS[tid] = bv;
    }

    // cp.async mapping: thread -> rows (tid>>2) and (tid>>2)+64, col (tid&3)*16B
    const int crow = tid >> 2;
    const size_t rstride = (size_t)K * 2;   // bytes per gmem row
    const int ccol = (tid & 3) * 16;

    const char* Ag  = (const char*)A   + (size_t)(bm + crow) * rstride + ccol;
    const char* BHg = (const char*)Bhi + (size_t)(bn + crow) * rstride + ccol;
    const char* BLg = (const char*)Blo + (size_t)(bn + crow) * rstride + ccol;
    const size_t r64 = 64 * rstride;

    const uint32_t sbase = tilesU + crow * ROWB + (tid & 3) * 16;

    // ldmatrix per-lane base addresses (within stage 0)
    //  A fragment (m16k16): lanes 0-15 -> rows, lanes 16-31 -> rows at k+8
    const uint32_t aAddr = tilesU + (wm + (lane & 15)) * ROWB + (lane >> 4) * 16;
    //  B fragment (two n8 tiles per x4): groups of 8 lanes ->
    //    (n0-7,k0),(n0-7,k8),(n8-15,k0),(n8-15,k8)
    const uint32_t bAddr = tilesU + TILE_B
                         + (wn + (lane >> 4) * 8 + (lane & 7)) * ROWB
                         + ((lane >> 3) & 1) * 16;

    float acc[4][4][4];
    #pragma unroll
    for (int mt = 0; mt < 4; mt++)
        #pragma unroll
        for (int nt = 0; nt < 4; nt++)
            #pragma unroll
            for (int j = 0; j < 4; j++)
                acc[mt][nt][j] = 0.0f;

    const int NK = K >> 5;

    auto load_stage = [&](int s, int kt) {
        uint32_t d = sbase + s * STAGE_B;
        size_t go = (size_t)kt * 64;     // 32 fp16 = 64 bytes
        cp_async16(d,                 Ag  + go);
        cp_async16(d + 64 * ROWB,     Ag  + go + r64);
        cp_async16(d + TILE_B,            BHg + go);
        cp_async16(d + TILE_B + 64 * ROWB, BHg + go + r64);
        cp_async16(d + 2 * TILE_B,            BLg + go);
        cp_async16(d + 2 * TILE_B + 64 * ROWB, BLg + go + r64);
    };

    load_stage(0, 0); CP_COMMIT();
    load_stage(1, 1); CP_COMMIT();

    for (int kt = 0; kt < NK; kt++) {
        CP_WAIT1();          // stage kt landed
        __syncthreads();     // visible to all; prev iter's MMA done

        if (kt + 2 < NK) load_stage((kt + 2) % 3, kt + 2);
        CP_COMMIT();         // unconditional: keeps group counting aligned

        const uint32_t stU = (kt % 3) * STAGE_B;

        #pragma unroll
        for (int ko = 0; ko < 2; ko++) {
            const uint32_t kb = stU + ko * 32;

            uint32_t Af[4][4];
            #pragma unroll
            for (int mt = 0; mt < 4; mt++)
                ldsm_x4(Af[mt][0], Af[mt][1], Af[mt][2], Af[mt][3],
                        aAddr + kb + mt * (16 * ROWB));

            uint32_t Bh[2][4], Bl[2][4];
            #pragma unroll
            for (int np = 0; np < 2; np++) {
                ldsm_x4(Bh[np][0], Bh[np][1], Bh[np][2], Bh[np][3],
                        bAddr + kb + np * (16 * ROWB));
                ldsm_x4(Bl[np][0], Bl[np][1], Bl[np][2], Bl[np][3],
                        bAddr + kb + np * (16 * ROWB) + TILE_B);
            }

            #pragma unroll
            for (int mt = 0; mt < 4; mt++)
                #pragma unroll
                for (int nt = 0; nt < 4; nt++) {
                    float* c = acc[mt][nt];
                    const int np = nt >> 1, pr = (nt & 1) * 2;
                    mma_f16(c, Af[mt][0], Af[mt][1], Af[mt][2], Af[mt][3],
                            Bh[np][pr], Bh[np][pr + 1]);
                    mma_f16(c, Af[mt][0], Af[mt][1], Af[mt][2], Af[mt][3],
                            Bl[np][pr], Bl[np][pr + 1]);
                }
        }
    }

    // Epilogue: scale + bias + float2 stores
    const int c0 = (lane & 3) * 2;
    #pragma unroll
    for (int mt = 0; mt < 4; mt++) {
        #pragma unroll
        for (int nt = 0; nt < 4; nt++) {
            int colL = wn + nt * 8 + c0;
            int col  = bn + colL;
            float b0v = biasS[colL];
            float b1v = biasS[colL + 1];
            int row0 = bm + wm + mt * 16 + g0;
            float2 v0 = make_float2(fmaf(acc[mt][nt][0], out_scale, b0v),
                                    fmaf(acc[mt][nt][1], out_scale, b1v));
            float2 v1 = make_float2(fmaf(acc[mt][nt][2], out_scale, b0v),
                                    fmaf(acc[mt][nt][3], out_scale, b1v));
            *(float2*)(C + (size_t)row0 * N + col)       = v0;
            *(float2*)(C + (size_t)(row0 + 8) * N + col) = v1;
        }
    }
}

// ---------------------------------------------------------------------------
// IndRNN scan, fp16 output with power-of-2 down-scaling (range protection):
//   O[b,t,h] = fp16( relu(P[b,t,h] + u[h]*h_prev) * store_scale )
// ---------------------------------------------------------------------------
__global__ void scan_relu_f16(const float* __restrict__ P,
                              const float* __restrict__ u,
                              __half* __restrict__ O,
                              float store_scale)
{
    int idx = blockIdx.x * blockDim.x + threadIdx.x;
    if (idx >= BB * HH) return;
    int b = idx / HH;
    int h = idx - b * HH;
    float uu = u[h];
    float hv = 0.0f;
    const float* p = P + (size_t)b * TT * HH + h;
    __half* o = O + (size_t)b * TT * HH + h;

    constexpr int U = 16;
    float x[U];
    #pragma unroll
    for (int i = 0; i < U; i++) x[i] = p[(size_t)i * HH];

    #pragma unroll 1
    for (int t = 0; t < TT; t += U) {
        float y[U];
        bool more = (t + U) < TT;
        const float* pn = p + (size_t)U * HH;
        if (more) {
            #pragma unroll
            for (int i = 0; i < U; i++) y[i] = pn[(size_t)i * HH];
        }
        #pragma unroll
        for (int i = 0; i < U; i++) {
            hv = fmaxf(fmaf(uu, hv, x[i]), 0.0f);
            o[(size_t)i * HH] = __float2half_rn(hv * store_scale);
        }
        #pragma unroll
        for (int i = 0; i < U; i++) x[i] = y[i];
        p = pn;
        o += (size_t)U * HH;
    }
}

// ---------------------------------------------------------------------------
// Converters
// ---------------------------------------------------------------------------
__global__ void f32_to_f16(const float* __restrict__ in,
                           __half* __restrict__ out, int n)
{
    int i = (blockIdx.x * blockDim.x + threadIdx.x) * 4;
    if (i < n) {
        float4 v = *(const float4*)(in + i);
        __half2 h0 = __floats2half2_rn(v.x, v.y);
        __half2 h1 = __floats2half2_rn(v.z, v.w);
        uint2 pk = make_uint2(*(uint32_t*)&h0, *(uint32_t*)&h1);
        *(uint2*)(out + i) = pk;
    }
}

__global__ void split_w_f16(const float* __restrict__ in,
                            __half* __restrict__ hi,
                            __half* __restrict__ lo, int n)
{
    int i = blockIdx.x * blockDim.x + threadIdx.x;
    if (i < n) {
        float w = in[i];
        __half h = __float2half_rn(w);
        hi[i] = h;
        lo[i] = __float2half_rn(w - __half2float(h));
    }
}

extern "C" void kernel_launch(void* const* d_in, const int* in_sizes, int n_in,
                              void* d_out, int out_size)
{
    const float* x    = (const float*)d_in[0];
    const float* W0   = (const float*)d_in[1];
    const float* bl0  = (const float*)d_in[2];
    const float* u0   = (const float*)d_in[3];
    const float* bb0  = (const float*)d_in[4];
    const float* W1   = (const float*)d_in[5];
    const float* bl1  = (const float*)d_in[6];
    const float* u1   = (const float*)d_in[7];
    const float* bb1  = (const float*)d_in[8];
    const float* fcW  = (const float*)d_in[9];
    const float* fcb  = (const float*)d_in[10];
    float* out = (float*)d_out;

    float  *proj;
    __half *act, *x16, *w0h, *w0l, *w1h, *w1l, *fwh, *fwl;
    cudaGetSymbolAddress((void**)&proj, g_proj);
    cudaGetSymbolAddress((void**)&act,  g_act);
    cudaGetSymbolAddress((void**)&x16,  g_x16);
    cudaGetSymbolAddress((void**)&w0h,  g_w0hi);
    cudaGetSymbolAddress((void**)&w0l,  g_w0lo);
    cudaGetSymbolAddress((void**)&w1h,  g_w1hi);
    cudaGetSymbolAddress((void**)&w1l,  g_w1lo);
    cudaGetSymbolAddress((void**)&fwh,  g_fwhi);
    cudaGetSymbolAddress((void**)&fwl,  g_fwlo);

    cudaFuncSetAttribute(gemm_f16_2t,
                         cudaFuncAttributeMaxDynamicSharedMemorySize,
                         SMEM_GEMM);

    // Pre-split weights (tiny)
    split_w_f16<<<(HH * DIN + 255) / 256, 256>>>(W0, w0h, w0l, HH * DIN);
    split_w_f16<<<(HH * HH + 255) / 256, 256>>>(W1, w1h, w1l, HH * HH);
    split_w_f16<<<(DOUT * HH + 255) / 256, 256>>>(fcW, fwh, fwl, DOUT * HH);

    // x -> fp16 (x ~ N(0,1): no range issue)
    {
        int n = MM * DIN;
        f32_to_f16<<<(n / 4 + 255) / 256, 256>>>(x, x16, n);
    }

    // GEMM0: proj = x16 @ W0^T + bl0 + bb0   [M, H], K=128
    {
        dim3 grid(HH / 128, MM / 128);
        gemm_f16_2t<<<grid, 256, SMEM_GEMM>>>(x16, w0h, w0l, bl0, bb0, proj,
                                              MM, HH, DIN, 1.0f);
    }
    // scan0 -> act = h1 * 2^-4
    scan_relu_f16<<<(BB * HH) / 128, 128>>>(proj, u0, act, 0.0625f);

    // GEMM1: proj = (h1*2^-4) @ W1^T * 16 + bl1 + bb1  [M, H], K=512
    {
        dim3 grid(HH / 128, MM / 128);
        gemm_f16_2t<<<grid, 256, SMEM_GEMM>>>(act, w1h, w1l, bl1, bb1, proj,
                                              MM, HH, HH, 16.0f);
    }
    // scan1 -> act = h2 * 2^-8
    scan_relu_f16<<<(BB * HH) / 128, 128>>>(proj, u1, act, 0.00390625f);

    // GEMM2: out = (h2*2^-8) @ fcW^T * 256 + fcb  [M, Dout], K=512
    {
        dim3 grid(DOUT / 128, MM / 128);
        gemm_f16_2t<<<grid, 256, SMEM_GEMM>>>(act, fwh, fwl, fcb, nullptr, out,
                                              MM, DOUT, HH, 256.0f);
    }
}

// round 7
// speedup vs baseline: 4.5707x; 1.3717x over previous
#include <cuda_runtime.h>
#include <cuda_fp16.h>
#include <cstdint>
#include <cstddef>

// Problem constants (fixed by the reference)
#define BB 64
#define TT 2048
#define DIN 128
#define HH 512
#define DOUT 128
#define MM (BB * TT)   // 131072

// Scratch buffers (allocation-guard-safe __device__ globals)
__device__ __align__(256) float  g_proj[(size_t)MM * HH];   // fp32 proj (both layers)
__device__ __align__(256) __half g_act[(size_t)MM * HH];    // fp16 activations (scaled)
__device__ __align__(256) __half g_x16[(size_t)MM * DIN];   // fp16 x
__device__ __align__(256) __half g_w0[HH * DIN];
__device__ __align__(256) __half g_w1[HH * HH];
__device__ __align__(256) __half g_fw[DOUT * HH];

// ---------------------------------------------------------------------------
// PTX helpers
// ---------------------------------------------------------------------------
__device__ __forceinline__ uint32_t smem_u32(const void* p) {
    uint32_t a;
    asm("{ .reg .u64 t; cvta.to.shared.u64 t, %1; cvt.u32.u64 %0, t; }"
        : "=r"(a) : "l"(p));
    return a;
}

__device__ __forceinline__ void cp_async16(uint32_t dst, const void* src) {
    asm volatile("cp.async.cg.shared.global [%0], [%1], 16;"
                 :: "r"(dst), "l"(src));
}
#define CP_COMMIT() asm volatile("cp.async.commit_group;" ::: "memory")
#define CP_WAIT1()  asm volatile("cp.async.wait_group 1;" ::: "memory")

// mma m16n8k16 fp16 inputs, fp32 accumulate (in place)
__device__ __forceinline__ void mma_f16(float* c,
                                        uint32_t a0, uint32_t a1,
                                        uint32_t a2, uint32_t a3,
                                        uint32_t b0, uint32_t b1) {
    asm volatile(
        "mma.sync.aligned.m16n8k16.row.col.f32.f16.f16.f32 "
        "{%0,%1,%2,%3}, {%4,%5,%6,%7}, {%8,%9}, {%0,%1,%2,%3};"
        : "+f"(c[0]), "+f"(c[1]), "+f"(c[2]), "+f"(c[3])
        : "r"(a0), "r"(a1), "r"(a2), "r"(a3), "r"(b0), "r"(b1));
}

// ldmatrix x4 (b16): four 8x8 tiles, one per 8-lane group
__device__ __forceinline__ void ldsm_x4(uint32_t& r0, uint32_t& r1,
                                        uint32_t& r2, uint32_t& r3,
                                        uint32_t addr) {
    asm volatile("ldmatrix.sync.aligned.m8n8.x4.shared.b16 {%0,%1,%2,%3}, [%4];"
                 : "=r"(r0), "=r"(r1), "=r"(r2), "=r"(r3) : "r"(addr));
}

// ---------------------------------------------------------------------------
// fp16 GEMM (NT): C[M,N] = out_scale * (A[M,K] * B[N,K]^T) + bias1 (+bias2)
// Block 128x128, BK=32, 8 warps (2x4), warp tile 64x32.
// cp.async 3-stage pipeline; ldmatrix fragment loads.
// smem rows: 32 fp16 = 64B data + 16B pad = 80B (conflict-free LDSM phases).
// ---------------------------------------------------------------------------
#define ROWB   80
#define TILE_B (128 * ROWB)        // 10240
#define STAGE_B (2 * TILE_B)       // 20480 (A, B)
#define NSTAGE 3
#define SMEM_GEMM (512 + NSTAGE * STAGE_B)   // 61952

__global__ __launch_bounds__(256, 2)
void gemm_f16(const __half* __restrict__ A,
              const __half* __restrict__ Bw,
              const float* __restrict__ bias1,
              const float* __restrict__ bias2,
              float* __restrict__ C,
              int M, int N, int K, float out_scale)
{
    extern __shared__ char smem[];
    float* biasS = (float*)smem;
    char* tiles = smem + 512;
    const uint32_t tilesU = smem_u32(tiles);

    const int tid  = threadIdx.x;
    const int wid  = tid >> 5;
    const int lane = tid & 31;
    const int bm = blockIdx.y * 128;
    const int bn = blockIdx.x * 128;

    const int wm = (wid >> 2) * 64;
    const int wn = (wid & 3) * 32;
    const int g0 = lane >> 2;

    if (tid < 128) {
        float bv = bias1[bn + tid];
        if (bias2) bv += bias2[bn + tid];
        biasS[tid] = bv;
    }

    // cp.async mapping: thread -> rows (tid>>2) and (tid>>2)+64, col (tid&3)*16B
    const int crow = tid >> 2;
    const size_t rstride = (size_t)K * 2;   // bytes per gmem row
    const int ccol = (tid & 3) * 16;

    const char* Ag = (const char*)A  + (size_t)(bm + crow) * rstride + ccol;
    const char* Bg = (const char*)Bw + (size_t)(bn + crow) * rstride + ccol;
    const size_t r64 = 64 * rstride;

    const uint32_t sbase = tilesU + crow * ROWB + (tid & 3) * 16;

    // ldmatrix per-lane base addresses (within stage 0)
    const uint32_t aAddr = tilesU + (wm + (lane & 15)) * ROWB + (lane >> 4) * 16;
    const uint32_t bAddr = tilesU + TILE_B
                         + (wn + (lane >> 4) * 8 + (lane & 7)) * ROWB
                         + ((lane >> 3) & 1) * 16;

    float acc[4][4][4];
    #pragma unroll
    for (int mt = 0; mt < 4; mt++)
        #pragma unroll
        for (int nt = 0; nt < 4; nt++)
            #pragma unroll
            for (int j = 0; j < 4; j++)
                acc[mt][nt][j] = 0.0f;

    const int NK = K >> 5;

    auto load_stage = [&](int s, int kt) {
        uint32_t d = sbase + s * STAGE_B;
        size_t go = (size_t)kt * 64;     // 32 fp16 = 64 bytes
        cp_async16(d,                 Ag + go);
        cp_async16(d + 64 * ROWB,     Ag + go + r64);
        cp_async16(d + TILE_B,            Bg + go);
        cp_async16(d + TILE_B + 64 * ROWB, Bg + go + r64);
    };

    load_stage(0, 0); CP_COMMIT();
    load_stage(1, 1); CP_COMMIT();

    for (int kt = 0; kt < NK; kt++) {
        CP_WAIT1();          // stage kt landed
        __syncthreads();     // visible to all; prev iter's MMA done

        if (kt + 2 < NK) load_stage((kt + 2) % 3, kt + 2);
        CP_COMMIT();         // unconditional: keeps group counting aligned

        const uint32_t stU = (kt % 3) * STAGE_B;

        #pragma unroll
        for (int ko = 0; ko < 2; ko++) {
            const uint32_t kb = stU + ko * 32;

            uint32_t Af[4][4];
            #pragma unroll
            for (int mt = 0; mt < 4; mt++)
                ldsm_x4(Af[mt][0], Af[mt][1], Af[mt][2], Af[mt][3],
                        aAddr + kb + mt * (16 * ROWB));

            uint32_t Bf[2][4];
            #pragma unroll
            for (int np = 0; np < 2; np++)
                ldsm_x4(Bf[np][0], Bf[np][1], Bf[np][2], Bf[np][3],
                        bAddr + kb + np * (16 * ROWB));

            #pragma unroll
            for (int mt = 0; mt < 4; mt++)
                #pragma unroll
                for (int nt = 0; nt < 4; nt++) {
                    const int np = nt >> 1, pr = (nt & 1) * 2;
                    mma_f16(acc[mt][nt],
                            Af[mt][0], Af[mt][1], Af[mt][2], Af[mt][3],
                            Bf[np][pr], Bf[np][pr + 1]);
                }
        }
    }

    // Epilogue: scale + bias + float2 stores
    const int c0 = (lane & 3) * 2;
    #pragma unroll
    for (int mt = 0; mt < 4; mt++) {
        #pragma unroll
        for (int nt = 0; nt < 4; nt++) {
            int colL = wn + nt * 8 + c0;
            int col  = bn + colL;
            float b0v = biasS[colL];
            float b1v = biasS[colL + 1];
            int row0 = bm + wm + mt * 16 + g0;
            float2 v0 = make_float2(fmaf(acc[mt][nt][0], out_scale, b0v),
                                    fmaf(acc[mt][nt][1], out_scale, b1v));
            float2 v1 = make_float2(fmaf(acc[mt][nt][2], out_scale, b0v),
                                    fmaf(acc[mt][nt][3], out_scale, b1v));
            *(float2*)(C + (size_t)row0 * N + col)       = v0;
            *(float2*)(C + (size_t)(row0 + 8) * N + col) = v1;
        }
    }
}

// ---------------------------------------------------------------------------
// IndRNN scan, fp16 output with power-of-2 down-scaling (range protection):
//   O[b,t,h] = fp16( relu(P[b,t,h] + u[h]*h_prev) * store_scale )
// ---------------------------------------------------------------------------
__global__ void scan_relu_f16(const float* __restrict__ P,
                              const float* __restrict__ u,
                              __half* __restrict__ O,
                              float store_scale)
{
    int idx = blockIdx.x * blockDim.x + threadIdx.x;
    if (idx >= BB * HH) return;
    int b = idx / HH;
    int h = idx - b * HH;
    float uu = u[h];
    float hv = 0.0f;
    const float* p = P + (size_t)b * TT * HH + h;
    __half* o = O + (size_t)b * TT * HH + h;

    constexpr int U = 16;
    float x[U];
    #pragma unroll
    for (int i = 0; i < U; i++) x[i] = p[(size_t)i * HH];

    #pragma unroll 1
    for (int t = 0; t < TT; t += U) {
        float y[U];
        bool more = (t + U) < TT;
        const float* pn = p + (size_t)U * HH;
        if (more) {
            #pragma unroll
            for (int i = 0; i < U; i++) y[i] = pn[(size_t)i * HH];
        }
        #pragma unroll
        for (int i = 0; i < U; i++) {
            hv = fmaxf(fmaf(uu, hv, x[i]), 0.0f);
            o[(size_t)i * HH] = __float2half_rn(hv * store_scale);
        }
        #pragma unroll
        for (int i = 0; i < U; i++) x[i] = y[i];
        p = pn;
        o += (size_t)U * HH;
    }
}

// ---------------------------------------------------------------------------
// Converter
// ---------------------------------------------------------------------------
__global__ void f32_to_f16(const float* __restrict__ in,
                           __half* __restrict__ out, int n)
{
    int i = (blockIdx.x * blockDim.x + threadIdx.x) * 4;
    if (i < n) {
        float4 v = *(const float4*)(in + i);
        __half2 h0 = __floats2half2_rn(v.x, v.y);
        __half2 h1 = __floats2half2_rn(v.z, v.w);
        uint2 pk = make_uint2(*(uint32_t*)&h0, *(uint32_t*)&h1);
        *(uint2*)(out + i) = pk;
    }
}

extern "C" void kernel_launch(void* const* d_in, const int* in_sizes, int n_in,
                              void* d_out, int out_size)
{
    const float* x    = (const float*)d_in[0];
    const float* W0   = (const float*)d_in[1];
    const float* bl0  = (const float*)d_in[2];
    const float* u0   = (const float*)d_in[3];
    const float* bb0  = (const float*)d_in[4];
    const float* W1   = (const float*)d_in[5];
    const float* bl1  = (const float*)d_in[6];
    const float* u1   = (const float*)d_in[7];
    const float* bb1  = (const float*)d_in[8];
    const float* fcW  = (const float*)d_in[9];
    const float* fcb  = (const float*)d_in[10];
    float* out = (float*)d_out;

    float  *proj;
    __half *act, *x16, *w0, *w1, *fw;
    cudaGetSymbolAddress((void**)&proj, g_proj);
    cudaGetSymbolAddress((void**)&act,  g_act);
    cudaGetSymbolAddress((void**)&x16,  g_x16);
    cudaGetSymbolAddress((void**)&w0,   g_w0);
    cudaGetSymbolAddress((void**)&w1,   g_w1);
    cudaGetSymbolAddress((void**)&fw,   g_fw);

    cudaFuncSetAttribute(gemm_f16,
                         cudaFuncAttributeMaxDynamicSharedMemorySize,
                         SMEM_GEMM);

    // Weights -> fp16 (tiny)
    f32_to_f16<<<(HH * DIN / 4 + 255) / 256, 256>>>(W0, w0, HH * DIN);
    f32_to_f16<<<(HH * HH / 4 + 255) / 256, 256>>>(W1, w1, HH * HH);
    f32_to_f16<<<(DOUT * HH / 4 + 255) / 256, 256>>>(fcW, fw, DOUT * HH);

    // x -> fp16 (x ~ N(0,1): no range issue)
    {
        int n = MM * DIN;
        f32_to_f16<<<(n / 4 + 255) / 256, 256>>>(x, x16, n);
    }

    // GEMM0: proj = x16 @ W0^T + bl0 + bb0   [M, H], K=128
    {
        dim3 grid(HH / 128, MM / 128);
        gemm_f16<<<grid, 256, SMEM_GEMM>>>(x16, w0, bl0, bb0, proj,
                                           MM, HH, DIN, 1.0f);
    }
    // scan0 -> act = h1 * 2^-4
    scan_relu_f16<<<(BB * HH) / 128, 128>>>(proj, u0, act, 0.0625f);

    // GEMM1: proj = (h1*2^-4) @ W1^T * 16 + bl1 + bb1  [M, H], K=512
    {
        dim3 grid(HH / 128, MM / 128);
        gemm_f16<<<grid, 256, SMEM_GEMM>>>(act, w1, bl1, bb1, proj,
                                           MM, HH, HH, 16.0f);
    }
    // scan1 -> act = h2 * 2^-8
    scan_relu_f16<<<(BB * HH) / 128, 128>>>(proj, u1, act, 0.00390625f);

    // GEMM2: out = (h2*2^-8) @ fcW^T * 256 + fcb  [M, Dout], K=512
    {
        dim3 grid(DOUT / 128, MM / 128);
        gemm_f16<<<grid, 256, SMEM_GEMM>>>(act, fw, fcb, nullptr, out,
                                           MM, DOUT, HH, 256.0f);
    }
}